// round 15
// baseline (speedup 1.0000x reference)
#include <cuda_runtime.h>
#include <cuda_bf16.h>
#include <cstdint>

#define NN   20000
#define EE   320000
#define DD   256

// ---------------- scratch (static device globals; no allocs allowed) ----------------
__device__ __align__(16) float g_hw[(size_t)NN * DD];
__device__ __align__(16) __nv_bfloat16 g_ahi [(size_t)NN * DD];   // split buffer S0
__device__ __align__(16) __nv_bfloat16 g_alo [(size_t)NN * DD];
__device__ __align__(16) __nv_bfloat16 g_a2hi[(size_t)NN * DD];   // split buffer S1 (x split)
__device__ __align__(16) __nv_bfloat16 g_a2lo[(size_t)NN * DD];
__device__ __align__(16) __nv_bfloat16 g_bhi[9 * DD * DD];        // slot0=W12, 2..7=Ws, 8=W3fold
__device__ __align__(16) __nv_bfloat16 g_blo[9 * DD * DD];
__device__ float g_dt[2 * NN];    // [0,NN): e_src totals, [NN,2NN): e_dst totals
__device__ int g_srcA[EE], g_dstA[EE], g_csrc[EE];
__device__ __align__(16) int g_deg[NN];
__device__ int g_rowptr[NN + 1], g_cursor[NN];
__device__ int g_is64;

// ---------------- helpers ----------------
__device__ __forceinline__ uint32_t smem_u32(const void* p) {
    uint32_t a;
    asm("{ .reg .u64 t; cvta.to.shared.u64 t, %1; cvt.u32.u64 %0, t; }" : "=r"(a) : "l"(p));
    return a;
}

// ---------------- parallel dtype detect ----------------
__global__ void k_detect(const int* ei32) {
    __shared__ int anynz;
    int t = threadIdx.x;                     // 128 threads
    if (t == 0) anynz = 0;
    __syncthreads();
    int nz = (ei32[2 * t + 1] != 0);
    if (__any_sync(0xFFFFFFFFu, nz) && (t & 31) == 0) atomicOr(&anynz, 1);
    __syncthreads();
    if (t == 0) g_is64 = anynz ? 0 : 1;      // all high words zero => int64
}

// ---------------- convert + degree count (one edge per thread) ----------------
__global__ void k_convert(const void* ei) {
    int i = blockIdx.x * blockDim.x + threadIdx.x;
    if (i >= EE) return;
    int s, t;
    if (g_is64) {
        const long long* p = (const long long*)ei;
        s = (int)p[i]; t = (int)p[EE + i];
    } else {
        const int* p = (const int*)ei;
        s = p[i]; t = p[EE + i];
    }
    g_srcA[i] = s; g_dstA[i] = t;
    atomicAdd(&g_deg[t], 1);
}

// ---------------- single-block warp-shuffle scan (NN = 1000 * 20) ----------------
__global__ void k_scan() {
    __shared__ int wsum[32];
    int t = threadIdx.x, lane = t & 31, w = t >> 5;
    int loc[20];
    int s = 0;
    if (t < 1000) {
        const int4* p = (const int4*)(g_deg + t * 20);
        #pragma unroll
        for (int i = 0; i < 5; i++) {
            int4 v = p[i];
            loc[4 * i]     = s; s += v.x;
            loc[4 * i + 1] = s; s += v.y;
            loc[4 * i + 2] = s; s += v.z;
            loc[4 * i + 3] = s; s += v.w;
        }
    }
    int inc = s;
    #pragma unroll
    for (int o = 1; o < 32; o <<= 1) {
        int v = __shfl_up_sync(0xFFFFFFFFu, inc, o);
        if (lane >= o) inc += v;
    }
    if (lane == 31) wsum[w] = inc;
    __syncthreads();
    if (w == 0) {
        int v = wsum[lane];
        int wi = v;
        #pragma unroll
        for (int o = 1; o < 32; o <<= 1) {
            int u = __shfl_up_sync(0xFFFFFFFFu, wi, o);
            if (lane >= o) wi += u;
        }
        wsum[lane] = wi - v;   // exclusive
    }
    __syncthreads();
    int excl = wsum[w] + (inc - s);
    if (t < 1000) {
        int base = t * 20;
        #pragma unroll
        for (int i = 0; i < 20; i++) {
            int r = excl + loc[i];
            g_rowptr[base + i] = r;
            g_cursor[base + i] = r;
        }
    }
    if (t == 0) g_rowptr[NN] = EE;
}

__global__ void k_fill() {
    int i = blockIdx.x * blockDim.x + threadIdx.x;
    if (i >= EE) return;
    int pos = atomicAdd(&g_cursor[g_dstA[i]], 1);
    g_csrc[pos] = g_srcA[i];
}

// ---------------- fp32 -> bf16 hi/lo split of x (into S1) ----------------
__global__ void k_convA(const float* __restrict__ src) {
    int i = blockIdx.x * blockDim.x + threadIdx.x;
    const int total = NN * DD / 8;
    if (i >= total) return;
    float4 v0 = ((const float4*)src)[2 * i];
    float4 v1 = ((const float4*)src)[2 * i + 1];
    float f[8] = {v0.x, v0.y, v0.z, v0.w, v1.x, v1.y, v1.z, v1.w};
    __nv_bfloat162 hp[4], lp[4];
    #pragma unroll
    for (int j = 0; j < 4; j++) {
        __nv_bfloat16 h0 = __float2bfloat16(f[2 * j]);
        __nv_bfloat16 h1 = __float2bfloat16(f[2 * j + 1]);
        hp[j] = __halves2bfloat162(h0, h1);
        lp[j] = __halves2bfloat162(__float2bfloat16(f[2 * j] - __bfloat162float(h0)),
                                   __float2bfloat16(f[2 * j + 1] - __bfloat162float(h1)));
    }
    *(uint4*)(g_a2hi + 8 * (size_t)i) = *(uint4*)hp;
    *(uint4*)(g_a2lo + 8 * (size_t)i) = *(uint4*)lp;
}

// ---------------- W12 = W1 @ W2 (fp32, 256^3), stored as B^T split into slot 0 ----------------
__global__ void k_w12(const float* __restrict__ W1, const float* __restrict__ W2) {
    __shared__ float As[16][16], Bs[16][17];
    int tx = threadIdx.x, ty = threadIdx.y;
    int k = blockIdx.y * 16 + ty;   // W12 row
    int n = blockIdx.x * 16 + tx;   // W12 col
    float acc = 0.f;
    for (int j0 = 0; j0 < DD; j0 += 16) {
        As[ty][tx] = W1[k * DD + j0 + tx];
        Bs[ty][tx] = W2[(j0 + ty) * DD + n];
        __syncthreads();
        #pragma unroll
        for (int j = 0; j < 16; j++) acc = fmaf(As[ty][j], Bs[j][tx], acc);
        __syncthreads();
    }
    __nv_bfloat16 h = __float2bfloat16(acc);
    g_bhi[n * DD + k] = h;
    g_blo[n * DD + k] = __float2bfloat16(acc - __bfloat162float(h));
}

// ---------------- weights -> B^T bf16 hi/lo split, slots 2..8 (slot 8 folds W3) ----------------
__global__ void k_prepAllB(const float* __restrict__ Ws, const float* __restrict__ W3) {
    int i = blockIdx.x * blockDim.x + threadIdx.x;
    if (i >= 7 * DD * DD) return;
    int slot = 2 + (i >> 16), idx = i & 65535;
    int n = idx >> 8, k = idx & 255;
    float v;
    if (slot < 8)  v = Ws[(size_t)(slot - 2) * DD * DD + k * DD + n];
    else           v = W3[k * DD + n] + W3[(k + DD) * DD + n];
    __nv_bfloat16 h = __float2bfloat16(v);
    g_bhi[(size_t)slot * DD * DD + idx] = h;
    g_blo[(size_t)slot * DD * DD + idx] = __float2bfloat16(v - __bfloat162float(h));
}

// ---------------- mma.sync bf16 GEMM: out[M,256] = A @ B (exact R11 kernel) ----------------
// CTA tile 64 rows x 128 cols, BK=32, 256 threads (2 m-warps x 4 n-warps), occ 3.
#define GT 256
#define STAGE_BYTES 24576
#define SMEM_BYTES  (2 * STAGE_BYTES)
#define MTILE 64

__device__ __forceinline__ uint32_t swz(int row, int chunk) {
    return (uint32_t)(row * 64 + ((chunk ^ ((row >> 1) & 3)) << 4));
}
__device__ __forceinline__ void cpa16(uint32_t dst, const void* src, int sz) {
    asm volatile("cp.async.cg.shared.global [%0], [%1], 16, %2;"
                 :: "r"(dst), "l"(src), "r"(sz) : "memory");
}
__device__ __forceinline__ void ldsm4(uint32_t* r, uint32_t addr) {
    asm volatile("ldmatrix.sync.aligned.m8n8.x4.shared.b16 {%0,%1,%2,%3}, [%4];"
                 : "=r"(r[0]), "=r"(r[1]), "=r"(r[2]), "=r"(r[3]) : "r"(addr));
}
__device__ __forceinline__ void mma_bf16(float* d, const uint32_t* a, uint32_t b0, uint32_t b1) {
    asm volatile("mma.sync.aligned.m16n8k16.row.col.f32.bf16.bf16.f32 "
                 "{%0,%1,%2,%3}, {%4,%5,%6,%7}, {%8,%9}, {%0,%1,%2,%3};"
                 : "+f"(d[0]), "+f"(d[1]), "+f"(d[2]), "+f"(d[3])
                 : "r"(a[0]), "r"(a[1]), "r"(a[2]), "r"(a[3]), "r"(b0), "r"(b1));
}

__device__ __forceinline__ void load_stage(uint32_t sb, int stage, int kk,
                                           int rowBase, int colBase, int tid,
                                           const __nv_bfloat16* ahi, const __nv_bfloat16* alo,
                                           const __nv_bfloat16* bhi, const __nv_bfloat16* blo) {
    uint32_t base = sb + stage * STAGE_BYTES;
    #pragma unroll
    for (int i = 0; i < 6; i++) {
        int id = i * GT + tid;           // 0..1535
        if (id < 512) {
            int mat = id >> 8, rem = id & 255;
            int row = rem >> 2, chunk = rem & 3;
            uint32_t dst = base + mat * 4096 + swz(row, chunk);
            const __nv_bfloat16* sbase = mat ? alo : ahi;
            int grow = rowBase + row;
            int ok = grow < NN;
            cpa16(dst, sbase + (size_t)(ok ? grow : 0) * DD + kk * 32 + chunk * 8, ok ? 16 : 0);
        } else {
            int idb = id - 512;
            int mat = idb >> 9, rem = idb & 511;
            int row = rem >> 2, chunk = rem & 3;
            uint32_t dst = base + 8192 + mat * 8192 + swz(row, chunk);
            const __nv_bfloat16* sbase = mat ? blo : bhi;
            cpa16(dst, sbase + (size_t)(colBase + row) * DD + kk * 32 + chunk * 8, 16);
        }
    }
}

__global__ void __launch_bounds__(GT, 3)
k_gemm_mma(float* __restrict__ out,
           const __nv_bfloat16* __restrict__ ahi, const __nv_bfloat16* __restrict__ alo,
           const __nv_bfloat16* __restrict__ bhi, const __nv_bfloat16* __restrict__ blo,
           __nv_bfloat16* __restrict__ ehi, __nv_bfloat16* __restrict__ elo,
           const float* __restrict__ asrc, const float* __restrict__ adst, int dots) {
    extern __shared__ char sm[];
    uint32_t sb = smem_u32(sm);
    const int tid = threadIdx.x, lane = tid & 31, wid = tid >> 5;
    const int warp_m = wid & 1;        // 2 m-warps of 32 rows
    const int warp_n = wid >> 1;       // 4 n-warps of 32 cols
    const int colBase = blockIdx.x * 128;
    const int rowBase = blockIdx.y * MTILE;

    float acc[2][4][4] = {};

    load_stage(sb, 0, 0, rowBase, colBase, tid, ahi, alo, bhi, blo);
    asm volatile("cp.async.commit_group;" ::: "memory");

    for (int s = 0; s < 8; s++) {
        if (s + 1 < 8) load_stage(sb, (s + 1) & 1, s + 1, rowBase, colBase, tid, ahi, alo, bhi, blo);
        asm volatile("cp.async.commit_group;" ::: "memory");
        asm volatile("cp.async.wait_group 1;" ::: "memory");
        __syncthreads();

        uint32_t stg = sb + (s & 1) * STAGE_BYTES;
        #pragma unroll
        for (int k16 = 0; k16 < 2; k16++) {
            int chunk = k16 * 2 + (lane >> 4);
            uint32_t ah[2][4], al[2][4];
            #pragma unroll
            for (int mf = 0; mf < 2; mf++) {
                int arow = warp_m * 32 + mf * 16 + (lane & 15);
                ldsm4(ah[mf], stg + 0    + swz(arow, chunk));
                ldsm4(al[mf], stg + 4096 + swz(arow, chunk));
            }
            #pragma unroll
            for (int nb = 0; nb < 2; nb++) {
                uint32_t bhr[4], blr[4];
                int brow = warp_n * 32 + nb * 16 + (lane & 15);
                ldsm4(bhr, stg + 8192  + swz(brow, chunk));
                ldsm4(blr, stg + 16384 + swz(brow, chunk));
                #pragma unroll
                for (int mf = 0; mf < 2; mf++)
                    #pragma unroll
                    for (int h = 0; h < 2; h++) {
                        float* d = acc[mf][nb * 2 + h];
                        mma_bf16(d, ah[mf], bhr[h], bhr[h + 2]);
                        mma_bf16(d, ah[mf], blr[h], blr[h + 2]);
                        mma_bf16(d, al[mf], bhr[h], bhr[h + 2]);
                    }
            }
        }
        __syncthreads();
    }

    // ---- epilogue: store C (+ optional split emit, + attention-dot atomics) ----
    #pragma unroll
    for (int mf = 0; mf < 2; mf++) {
        int r0 = rowBase + warp_m * 32 + mf * 16 + (lane >> 2);
        float s0 = 0.f, s1 = 0.f, d0 = 0.f, d1 = 0.f;
        #pragma unroll
        for (int nf = 0; nf < 4; nf++) {
            int col = colBase + warp_n * 32 + nf * 8 + (lane & 3) * 2;
            #pragma unroll
            for (int half = 0; half < 2; half++) {
                int r = r0 + half * 8;
                if (r < NN) {
                    float v0 = acc[mf][nf][2 * half], v1 = acc[mf][nf][2 * half + 1];
                    *(float2*)(out + (size_t)r * DD + col) = make_float2(v0, v1);
                    if (ehi) {
                        __nv_bfloat16 h0 = __float2bfloat16(v0);
                        __nv_bfloat16 h1 = __float2bfloat16(v1);
                        *(__nv_bfloat162*)(ehi + (size_t)r * DD + col) = __halves2bfloat162(h0, h1);
                        *(__nv_bfloat162*)(elo + (size_t)r * DD + col) = __halves2bfloat162(
                            __float2bfloat16(v0 - __bfloat162float(h0)),
                            __float2bfloat16(v1 - __bfloat162float(h1)));
                    }
                }
            }
            if (dots) {
                float as0 = asrc[col], as1 = asrc[col + 1];
                float ad0 = adst[col], ad1 = adst[col + 1];
                s0 = fmaf(acc[mf][nf][0], as0, fmaf(acc[mf][nf][1], as1, s0));
                d0 = fmaf(acc[mf][nf][0], ad0, fmaf(acc[mf][nf][1], ad1, d0));
                s1 = fmaf(acc[mf][nf][2], as0, fmaf(acc[mf][nf][3], as1, s1));
                d1 = fmaf(acc[mf][nf][2], ad0, fmaf(acc[mf][nf][3], ad1, d1));
            }
        }
        if (dots) {
            #pragma unroll
            for (int o = 1; o <= 2; o <<= 1) {
                s0 += __shfl_xor_sync(0xFFFFFFFFu, s0, o);
                s1 += __shfl_xor_sync(0xFFFFFFFFu, s1, o);
                d0 += __shfl_xor_sync(0xFFFFFFFFu, d0, o);
                d1 += __shfl_xor_sync(0xFFFFFFFFu, d1, o);
            }
            if ((lane & 3) == 0) {
                if (r0 < NN)     { atomicAdd(&g_dt[r0], s0);     atomicAdd(&g_dt[NN + r0], d0); }
                if (r0 + 8 < NN) { atomicAdd(&g_dt[r0 + 8], s1); atomicAdd(&g_dt[NN + r0 + 8], d1); }
            }
        }
    }
}

// ---------------- fused GAT aggregate ----------------
#define MAXE 64
__global__ void __launch_bounds__(256)
k_gat(const float* __restrict__ bias, int dorelu) {
    __shared__ float sv[8][MAXE];
    __shared__ int   ss[8][MAXE];
    int wid = threadIdx.x >> 5, lane = threadIdx.x & 31;
    int n = blockIdx.x * 8 + wid;
    if (n >= NN) return;
    int start = g_rowptr[n], end = g_rowptr[n + 1];
    int deg = end - start;
    float ed = g_dt[NN + n];

    float acc[8] = {};
    float acc2[8] = {};
    float sum = 0.f;
    float m = -3.4e38f;

    if (deg <= MAXE) {
        for (int j0 = 0; j0 < deg; j0 += 32) {
            int j = j0 + lane;
            float v = -3.4e38f;
            if (j < deg) {
                int s = g_csrc[start + j];
                v = g_dt[s] + ed;
                v = v > 0.f ? v : 0.2f * v;
                sv[wid][j] = v;
                ss[wid][j] = s;
            }
            m = fmaxf(m, v);
        }
        #pragma unroll
        for (int o = 16; o > 0; o >>= 1) m = fmaxf(m, __shfl_xor_sync(0xFFFFFFFFu, m, o));
        __syncwarp();
        int j = 0;
        for (; j + 1 < deg; j += 2) {
            float ee0 = __expf(sv[wid][j] - m);
            float ee1 = __expf(sv[wid][j + 1] - m);
            sum += ee0 + ee1;
            const float4* row0 = (const float4*)(g_hw + (size_t)ss[wid][j] * DD);
            const float4* row1 = (const float4*)(g_hw + (size_t)ss[wid][j + 1] * DD);
            float4 a0 = row0[lane], b0 = row0[lane + 32];
            float4 a1 = row1[lane], b1 = row1[lane + 32];
            acc[0] = fmaf(ee0, a0.x, acc[0]);  acc[1] = fmaf(ee0, a0.y, acc[1]);
            acc[2] = fmaf(ee0, a0.z, acc[2]);  acc[3] = fmaf(ee0, a0.w, acc[3]);
            acc[4] = fmaf(ee0, b0.x, acc[4]);  acc[5] = fmaf(ee0, b0.y, acc[5]);
            acc[6] = fmaf(ee0, b0.z, acc[6]);  acc[7] = fmaf(ee0, b0.w, acc[7]);
            acc2[0] = fmaf(ee1, a1.x, acc2[0]); acc2[1] = fmaf(ee1, a1.y, acc2[1]);
            acc2[2] = fmaf(ee1, a1.z, acc2[2]); acc2[3] = fmaf(ee1, a1.w, acc2[3]);
            acc2[4] = fmaf(ee1, b1.x, acc2[4]); acc2[5] = fmaf(ee1, b1.y, acc2[5]);
            acc2[6] = fmaf(ee1, b1.z, acc2[6]); acc2[7] = fmaf(ee1, b1.w, acc2[7]);
        }
        if (j < deg) {
            float ee = __expf(sv[wid][j] - m);
            sum += ee;
            const float4* row = (const float4*)(g_hw + (size_t)ss[wid][j] * DD);
            float4 a = row[lane], b = row[lane + 32];
            acc[0] = fmaf(ee, a.x, acc[0]); acc[1] = fmaf(ee, a.y, acc[1]);
            acc[2] = fmaf(ee, a.z, acc[2]); acc[3] = fmaf(ee, a.w, acc[3]);
            acc[4] = fmaf(ee, b.x, acc[4]); acc[5] = fmaf(ee, b.y, acc[5]);
            acc[6] = fmaf(ee, b.z, acc[6]); acc[7] = fmaf(ee, b.w, acc[7]);
        }
        #pragma unroll
        for (int q = 0; q < 8; q++) acc[q] += acc2[q];
    } else {
        for (int j = start + lane; j < end; j += 32) {
            float v = g_dt[g_csrc[j]] + ed;
            v = v > 0.f ? v : 0.2f * v;
            m = fmaxf(m, v);
        }
        #pragma unroll
        for (int o = 16; o > 0; o >>= 1) m = fmaxf(m, __shfl_xor_sync(0xFFFFFFFFu, m, o));
        for (int j = start; j < end; j++) {
            int s = g_csrc[j];
            float v = g_dt[s] + ed;
            v = v > 0.f ? v : 0.2f * v;
            float ee = __expf(v - m);
            sum += ee;
            const float4* row = (const float4*)(g_hw + (size_t)s * DD);
            float4 a = row[lane], b = row[lane + 32];
            acc[0] = fmaf(ee, a.x, acc[0]); acc[1] = fmaf(ee, a.y, acc[1]);
            acc[2] = fmaf(ee, a.z, acc[2]); acc[3] = fmaf(ee, a.w, acc[3]);
            acc[4] = fmaf(ee, b.x, acc[4]); acc[5] = fmaf(ee, b.y, acc[5]);
            acc[6] = fmaf(ee, b.z, acc[6]); acc[7] = fmaf(ee, b.w, acc[7]);
        }
    }
    float inv = (deg > 0) ? 1.0f / sum : 0.f;

    float4 b0 = ((const float4*)bias)[lane];
    float4 b1 = ((const float4*)bias)[lane + 32];
    float o[8] = {acc[0] * inv + b0.x, acc[1] * inv + b0.y,
                  acc[2] * inv + b0.z, acc[3] * inv + b0.w,
                  acc[4] * inv + b1.x, acc[5] * inv + b1.y,
                  acc[6] * inv + b1.z, acc[7] * inv + b1.w};
    if (dorelu) {
        #pragma unroll
        for (int j = 0; j < 8; j++) o[j] = fmaxf(o[j], 0.f);
    }
    __nv_bfloat162 hp[4], lp[4];
    #pragma unroll
    for (int j = 0; j < 4; j++) {
        __nv_bfloat16 h0 = __float2bfloat16(o[2 * j]);
        __nv_bfloat16 h1 = __float2bfloat16(o[2 * j + 1]);
        hp[j] = __halves2bfloat162(h0, h1);
        lp[j] = __halves2bfloat162(__float2bfloat16(o[2 * j] - __bfloat162float(h0)),
                                   __float2bfloat16(o[2 * j + 1] - __bfloat162float(h1)));
    }
    __nv_bfloat16* dh = g_ahi + (size_t)n * DD;
    __nv_bfloat16* dl = g_alo + (size_t)n * DD;
    *(uint2*)(dh + 4 * lane)       = make_uint2(((uint2*)hp)[0].x, ((uint2*)hp)[0].y);
    *(uint2*)(dh + 128 + 4 * lane) = make_uint2(((uint2*)hp)[1].x, ((uint2*)hp)[1].y);
    *(uint2*)(dl + 4 * lane)       = make_uint2(((uint2*)lp)[0].x, ((uint2*)lp)[0].y);
    *(uint2*)(dl + 128 + 4 * lane) = make_uint2(((uint2*)lp)[1].x, ((uint2*)lp)[1].y);
}

// ---------------- launch ----------------
extern "C" void kernel_launch(void* const* d_in, const int* in_sizes, int n_in,
                              void* d_out, int out_size) {
    const float* x     = (const float*)d_in[0];
    const void*  ei    = d_in[1];
    const float* W1    = (const float*)d_in[2];
    const float* W2    = (const float*)d_in[3];
    const float* Ws    = (const float*)d_in[4];
    const float* a_src = (const float*)d_in[5];
    const float* a_dst = (const float*)d_in[6];
    const float* bias  = (const float*)d_in[7];
    const float* W3    = (const float*)d_in[8];
    float* out = (float*)d_out;

    float *p_hw, *p_dt;
    int* p_deg;
    __nv_bfloat16 *p_ahi, *p_alo, *p_a2hi, *p_a2lo, *p_bhi, *p_blo;
    cudaGetSymbolAddress((void**)&p_hw,   g_hw);
    cudaGetSymbolAddress((void**)&p_dt,   g_dt);
    cudaGetSymbolAddress((void**)&p_deg,  g_deg);
    cudaGetSymbolAddress((void**)&p_ahi,  g_ahi);
    cudaGetSymbolAddress((void**)&p_alo,  g_alo);
    cudaGetSymbolAddress((void**)&p_a2hi, g_a2hi);
    cudaGetSymbolAddress((void**)&p_a2lo, g_a2lo);
    cudaGetSymbolAddress((void**)&p_bhi,  g_bhi);
    cudaGetSymbolAddress((void**)&p_blo,  g_blo);

    cudaFuncSetAttribute(k_gemm_mma, cudaFuncAttributeMaxDynamicSharedMemorySize, SMEM_BYTES);

    // one-time: indices, CSR, x split, W12 product, weight splits
    k_detect<<<1, 128>>>((const int*)ei);
    cudaMemsetAsync(p_deg, 0, NN * sizeof(int));
    k_convert<<<(EE + 255) / 256, 256>>>(ei);
    k_scan<<<1, 1024>>>();
    k_fill<<<(EE + 255) / 256, 256>>>();
    k_convA<<<(NN * DD / 8 + 255) / 256, 256>>>(x);
    k_w12<<<dim3(16, 16), dim3(16, 16)>>>(W1, W2);
    k_prepAllB<<<(7 * DD * DD + 255) / 256, 256>>>(Ws, W3);

    dim3 gg(2, (NN + MTILE - 1) / MTILE);   // (2, 313)
    const int BW = DD * DD;

    // h = x @ (W1*W2): one GEMM (out store is dead but kept for binary parity), split into S0
    k_gemm_mma<<<gg, GT, SMEM_BYTES>>>(p_hw, p_a2hi, p_a2lo, p_bhi, p_blo,
                                       p_ahi, p_alo, nullptr, nullptr, 0);

    for (int l = 0; l < 6; l++) {
        cudaMemsetAsync(p_dt, 0, 2 * NN * sizeof(float));
        k_gemm_mma<<<gg, GT, SMEM_BYTES>>>(p_hw, p_ahi, p_alo,
                                           p_bhi + (size_t)(2 + l) * BW, p_blo + (size_t)(2 + l) * BW,
                                           nullptr, nullptr, a_src + l * DD, a_dst + l * DD, 1);
        k_gat<<<(NN + 7) / 8, 256>>>(bias + l * DD, l == 5 ? 1 : 0);
    }

    // out = relu(h) @ (W3_top + W3_bot)   (relu folded into last k_gat's split)
    k_gemm_mma<<<gg, GT, SMEM_BYTES>>>(out, p_ahi, p_alo, p_bhi + 8 * BW, p_blo + 8 * BW,
                                       nullptr, nullptr, nullptr, nullptr, 0);
}

// round 17
// speedup vs baseline: 1.0642x; 1.0642x over previous
#include <cuda_runtime.h>
#include <cuda_bf16.h>
#include <cuda_fp16.h>
#include <cstdint>

#define NN   20000
#define EE   320000
#define DD   256

// ---------------- scratch (static device globals; no allocs allowed) ----------------
__device__ __align__(16) __half g_hwh[(size_t)NN * DD];           // hw in fp16 (gather operand)
__device__ __align__(16) __nv_bfloat16 g_ahi [(size_t)NN * DD];   // split buffer S0
__device__ __align__(16) __nv_bfloat16 g_alo [(size_t)NN * DD];
__device__ __align__(16) __nv_bfloat16 g_a2hi[(size_t)NN * DD];   // split buffer S1 (x split)
__device__ __align__(16) __nv_bfloat16 g_a2lo[(size_t)NN * DD];
__device__ __align__(16) __nv_bfloat16 g_bhi[9 * DD * DD];        // slot0=W12, 2..7=Ws, 8=W3fold
__device__ __align__(16) __nv_bfloat16 g_blo[9 * DD * DD];
__device__ float g_dt[2 * NN];    // [0,NN): e_src totals, [NN,2NN): e_dst totals
__device__ int g_srcA[EE], g_dstA[EE], g_csrc[EE];
__device__ __align__(16) int g_deg[NN];
__device__ int g_rowptr[NN + 1], g_cursor[NN];
__device__ int g_is64;

// ---------------- helpers ----------------
__device__ __forceinline__ uint32_t smem_u32(const void* p) {
    uint32_t a;
    asm("{ .reg .u64 t; cvta.to.shared.u64 t, %1; cvt.u32.u64 %0, t; }" : "=r"(a) : "l"(p));
    return a;
}

// ---------------- parallel dtype detect ----------------
__global__ void k_detect(const int* ei32) {
    __shared__ int anynz;
    int t = threadIdx.x;                     // 128 threads
    if (t == 0) anynz = 0;
    __syncthreads();
    int nz = (ei32[2 * t + 1] != 0);
    if (__any_sync(0xFFFFFFFFu, nz) && (t & 31) == 0) atomicOr(&anynz, 1);
    __syncthreads();
    if (t == 0) g_is64 = anynz ? 0 : 1;      // all high words zero => int64
}

// ---------------- convert + degree count (one edge per thread) ----------------
__global__ void k_convert(const void* ei) {
    int i = blockIdx.x * blockDim.x + threadIdx.x;
    if (i >= EE) return;
    int s, t;
    if (g_is64) {
        const long long* p = (const long long*)ei;
        s = (int)p[i]; t = (int)p[EE + i];
    } else {
        const int* p = (const int*)ei;
        s = p[i]; t = p[EE + i];
    }
    g_srcA[i] = s; g_dstA[i] = t;
    atomicAdd(&g_deg[t], 1);
}

// ---------------- single-block warp-shuffle scan (NN = 1000 * 20) ----------------
__global__ void k_scan() {
    __shared__ int wsum[32];
    int t = threadIdx.x, lane = t & 31, w = t >> 5;
    int loc[20];
    int s = 0;
    if (t < 1000) {
        const int4* p = (const int4*)(g_deg + t * 20);
        #pragma unroll
        for (int i = 0; i < 5; i++) {
            int4 v = p[i];
            loc[4 * i]     = s; s += v.x;
            loc[4 * i + 1] = s; s += v.y;
            loc[4 * i + 2] = s; s += v.z;
            loc[4 * i + 3] = s; s += v.w;
        }
    }
    int inc = s;
    #pragma unroll
    for (int o = 1; o < 32; o <<= 1) {
        int v = __shfl_up_sync(0xFFFFFFFFu, inc, o);
        if (lane >= o) inc += v;
    }
    if (lane == 31) wsum[w] = inc;
    __syncthreads();
    if (w == 0) {
        int v = wsum[lane];
        int wi = v;
        #pragma unroll
        for (int o = 1; o < 32; o <<= 1) {
            int u = __shfl_up_sync(0xFFFFFFFFu, wi, o);
            if (lane >= o) wi += u;
        }
        wsum[lane] = wi - v;   // exclusive
    }
    __syncthreads();
    int excl = wsum[w] + (inc - s);
    if (t < 1000) {
        int base = t * 20;
        #pragma unroll
        for (int i = 0; i < 20; i++) {
            int r = excl + loc[i];
            g_rowptr[base + i] = r;
            g_cursor[base + i] = r;
        }
    }
    if (t == 0) g_rowptr[NN] = EE;
}

__global__ void k_fill() {
    int i = blockIdx.x * blockDim.x + threadIdx.x;
    if (i >= EE) return;
    int pos = atomicAdd(&g_cursor[g_dstA[i]], 1);
    g_csrc[pos] = g_srcA[i];
}

// ---------------- fp32 -> bf16 hi/lo split of x (into S1) ----------------
__global__ void k_convA(const float* __restrict__ src) {
    int i = blockIdx.x * blockDim.x + threadIdx.x;
    const int total = NN * DD / 8;
    if (i >= total) return;
    float4 v0 = ((const float4*)src)[2 * i];
    float4 v1 = ((const float4*)src)[2 * i + 1];
    float f[8] = {v0.x, v0.y, v0.z, v0.w, v1.x, v1.y, v1.z, v1.w};
    __nv_bfloat162 hp[4], lp[4];
    #pragma unroll
    for (int j = 0; j < 4; j++) {
        __nv_bfloat16 h0 = __float2bfloat16(f[2 * j]);
        __nv_bfloat16 h1 = __float2bfloat16(f[2 * j + 1]);
        hp[j] = __halves2bfloat162(h0, h1);
        lp[j] = __halves2bfloat162(__float2bfloat16(f[2 * j] - __bfloat162float(h0)),
                                   __float2bfloat16(f[2 * j + 1] - __bfloat162float(h1)));
    }
    *(uint4*)(g_a2hi + 8 * (size_t)i) = *(uint4*)hp;
    *(uint4*)(g_a2lo + 8 * (size_t)i) = *(uint4*)lp;
}

// ---------------- W12 = W1 @ W2 (fp32, 256^3), stored as B^T split into slot 0 ----------------
__global__ void k_w12(const float* __restrict__ W1, const float* __restrict__ W2) {
    __shared__ float As[16][16], Bs[16][17];
    int tx = threadIdx.x, ty = threadIdx.y;
    int k = blockIdx.y * 16 + ty;   // W12 row
    int n = blockIdx.x * 16 + tx;   // W12 col
    float acc = 0.f;
    for (int j0 = 0; j0 < DD; j0 += 16) {
        As[ty][tx] = W1[k * DD + j0 + tx];
        Bs[ty][tx] = W2[(j0 + ty) * DD + n];
        __syncthreads();
        #pragma unroll
        for (int j = 0; j < 16; j++) acc = fmaf(As[ty][j], Bs[j][tx], acc);
        __syncthreads();
    }
    __nv_bfloat16 h = __float2bfloat16(acc);
    g_bhi[n * DD + k] = h;
    g_blo[n * DD + k] = __float2bfloat16(acc - __bfloat162float(h));
}

// ---------------- weights -> B^T bf16 hi/lo split, slots 2..8 (slot 8 folds W3) ----------------
__global__ void k_prepAllB(const float* __restrict__ Ws, const float* __restrict__ W3) {
    int i = blockIdx.x * blockDim.x + threadIdx.x;
    if (i >= 7 * DD * DD) return;
    int slot = 2 + (i >> 16), idx = i & 65535;
    int n = idx >> 8, k = idx & 255;
    float v;
    if (slot < 8)  v = Ws[(size_t)(slot - 2) * DD * DD + k * DD + n];
    else           v = W3[k * DD + n] + W3[(k + DD) * DD + n];
    __nv_bfloat16 h = __float2bfloat16(v);
    g_bhi[(size_t)slot * DD * DD + idx] = h;
    g_blo[(size_t)slot * DD * DD + idx] = __float2bfloat16(v - __bfloat162float(h));
}

// ---------------- mma.sync bf16 GEMM: out[M,256] = A @ B ----------------
// CTA tile 64 rows x 128 cols, BK=32, 256 threads (2 m-warps x 4 n-warps), occ 3.
// MODE 0: emit bf16 hi/lo split only.  MODE 1: fp16 out + attention dots.  MODE 2: fp32 out.
#define GT 256
#define STAGE_BYTES 24576
#define SMEM_BYTES  (2 * STAGE_BYTES)
#define MTILE 64

__device__ __forceinline__ uint32_t swz(int row, int chunk) {
    return (uint32_t)(row * 64 + ((chunk ^ ((row >> 1) & 3)) << 4));
}
__device__ __forceinline__ void cpa16(uint32_t dst, const void* src, int sz) {
    asm volatile("cp.async.cg.shared.global [%0], [%1], 16, %2;"
                 :: "r"(dst), "l"(src), "r"(sz) : "memory");
}
__device__ __forceinline__ void ldsm4(uint32_t* r, uint32_t addr) {
    asm volatile("ldmatrix.sync.aligned.m8n8.x4.shared.b16 {%0,%1,%2,%3}, [%4];"
                 : "=r"(r[0]), "=r"(r[1]), "=r"(r[2]), "=r"(r[3]) : "r"(addr));
}
__device__ __forceinline__ void mma_bf16(float* d, const uint32_t* a, uint32_t b0, uint32_t b1) {
    asm volatile("mma.sync.aligned.m16n8k16.row.col.f32.bf16.bf16.f32 "
                 "{%0,%1,%2,%3}, {%4,%5,%6,%7}, {%8,%9}, {%0,%1,%2,%3};"
                 : "+f"(d[0]), "+f"(d[1]), "+f"(d[2]), "+f"(d[3])
                 : "r"(a[0]), "r"(a[1]), "r"(a[2]), "r"(a[3]), "r"(b0), "r"(b1));
}

__device__ __forceinline__ void load_stage(uint32_t sb, int stage, int kk,
                                           int rowBase, int colBase, int tid,
                                           const __nv_bfloat16* ahi, const __nv_bfloat16* alo,
                                           const __nv_bfloat16* bhi, const __nv_bfloat16* blo) {
    uint32_t base = sb + stage * STAGE_BYTES;
    #pragma unroll
    for (int i = 0; i < 6; i++) {
        int id = i * GT + tid;           // 0..1535
        if (id < 512) {
            int mat = id >> 8, rem = id & 255;
            int row = rem >> 2, chunk = rem & 3;
            uint32_t dst = base + mat * 4096 + swz(row, chunk);
            const __nv_bfloat16* sbase = mat ? alo : ahi;
            int grow = rowBase + row;
            int ok = grow < NN;
            cpa16(dst, sbase + (size_t)(ok ? grow : 0) * DD + kk * 32 + chunk * 8, ok ? 16 : 0);
        } else {
            int idb = id - 512;
            int mat = idb >> 9, rem = idb & 511;
            int row = rem >> 2, chunk = rem & 3;
            uint32_t dst = base + 8192 + mat * 8192 + swz(row, chunk);
            const __nv_bfloat16* sbase = mat ? blo : bhi;
            cpa16(dst, sbase + (size_t)(colBase + row) * DD + kk * 32 + chunk * 8, 16);
        }
    }
}

template <int MODE>
__global__ void __launch_bounds__(GT, 3)
k_gemm_mma(float* __restrict__ out, __half* __restrict__ outh,
           const __nv_bfloat16* __restrict__ ahi, const __nv_bfloat16* __restrict__ alo,
           const __nv_bfloat16* __restrict__ bhi, const __nv_bfloat16* __restrict__ blo,
           __nv_bfloat16* __restrict__ ehi, __nv_bfloat16* __restrict__ elo,
           const float* __restrict__ asrc, const float* __restrict__ adst) {
    extern __shared__ char sm[];
    uint32_t sb = smem_u32(sm);
    const int tid = threadIdx.x, lane = tid & 31, wid = tid >> 5;
    const int warp_m = wid & 1;        // 2 m-warps of 32 rows
    const int warp_n = wid >> 1;       // 4 n-warps of 32 cols
    const int colBase = blockIdx.x * 128;
    const int rowBase = blockIdx.y * MTILE;

    float acc[2][4][4] = {};

    load_stage(sb, 0, 0, rowBase, colBase, tid, ahi, alo, bhi, blo);
    asm volatile("cp.async.commit_group;" ::: "memory");

    for (int s = 0; s < 8; s++) {
        if (s + 1 < 8) load_stage(sb, (s + 1) & 1, s + 1, rowBase, colBase, tid, ahi, alo, bhi, blo);
        asm volatile("cp.async.commit_group;" ::: "memory");
        asm volatile("cp.async.wait_group 1;" ::: "memory");
        __syncthreads();

        uint32_t stg = sb + (s & 1) * STAGE_BYTES;
        #pragma unroll
        for (int k16 = 0; k16 < 2; k16++) {
            int chunk = k16 * 2 + (lane >> 4);
            uint32_t ah[2][4], al[2][4];
            #pragma unroll
            for (int mf = 0; mf < 2; mf++) {
                int arow = warp_m * 32 + mf * 16 + (lane & 15);
                ldsm4(ah[mf], stg + 0    + swz(arow, chunk));
                ldsm4(al[mf], stg + 4096 + swz(arow, chunk));
            }
            #pragma unroll
            for (int nb = 0; nb < 2; nb++) {
                uint32_t bhr[4], blr[4];
                int brow = warp_n * 32 + nb * 16 + (lane & 15);
                ldsm4(bhr, stg + 8192  + swz(brow, chunk));
                ldsm4(blr, stg + 16384 + swz(brow, chunk));
                #pragma unroll
                for (int mf = 0; mf < 2; mf++)
                    #pragma unroll
                    for (int h = 0; h < 2; h++) {
                        float* d = acc[mf][nb * 2 + h];
                        mma_bf16(d, ah[mf], bhr[h], bhr[h + 2]);
                        mma_bf16(d, ah[mf], blr[h], blr[h + 2]);
                        mma_bf16(d, al[mf], bhr[h], bhr[h + 2]);
                    }
            }
        }
        __syncthreads();
    }

    // ---- epilogue ----
    #pragma unroll
    for (int mf = 0; mf < 2; mf++) {
        int r0 = rowBase + warp_m * 32 + mf * 16 + (lane >> 2);
        float s0 = 0.f, s1 = 0.f, d0 = 0.f, d1 = 0.f;
        #pragma unroll
        for (int nf = 0; nf < 4; nf++) {
            int col = colBase + warp_n * 32 + nf * 8 + (lane & 3) * 2;
            #pragma unroll
            for (int half = 0; half < 2; half++) {
                int r = r0 + half * 8;
                if (r < NN) {
                    float v0 = acc[mf][nf][2 * half], v1 = acc[mf][nf][2 * half + 1];
                    if (MODE == 2)
                        *(float2*)(out + (size_t)r * DD + col) = make_float2(v0, v1);
                    if (MODE == 1)
                        *(__half2*)(outh + (size_t)r * DD + col) = __floats2half2_rn(v0, v1);
                    if (MODE == 0) {
                        __nv_bfloat16 h0 = __float2bfloat16(v0);
                        __nv_bfloat16 h1 = __float2bfloat16(v1);
                        *(__nv_bfloat162*)(ehi + (size_t)r * DD + col) = __halves2bfloat162(h0, h1);
                        *(__nv_bfloat162*)(elo + (size_t)r * DD + col) = __halves2bfloat162(
                            __float2bfloat16(v0 - __bfloat162float(h0)),
                            __float2bfloat16(v1 - __bfloat162float(h1)));
                    }
                }
            }
            if (MODE == 1) {
                float as0 = asrc[col], as1 = asrc[col + 1];
                float ad0 = adst[col], ad1 = adst[col + 1];
                s0 = fmaf(acc[mf][nf][0], as0, fmaf(acc[mf][nf][1], as1, s0));
                d0 = fmaf(acc[mf][nf][0], ad0, fmaf(acc[mf][nf][1], ad1, d0));
                s1 = fmaf(acc[mf][nf][2], as0, fmaf(acc[mf][nf][3], as1, s1));
                d1 = fmaf(acc[mf][nf][2], ad0, fmaf(acc[mf][nf][3], ad1, d1));
            }
        }
        if (MODE == 1) {
            #pragma unroll
            for (int o = 1; o <= 2; o <<= 1) {
                s0 += __shfl_xor_sync(0xFFFFFFFFu, s0, o);
                s1 += __shfl_xor_sync(0xFFFFFFFFu, s1, o);
                d0 += __shfl_xor_sync(0xFFFFFFFFu, d0, o);
                d1 += __shfl_xor_sync(0xFFFFFFFFu, d1, o);
            }
            if ((lane & 3) == 0) {
                if (r0 < NN)     { atomicAdd(&g_dt[r0], s0);     atomicAdd(&g_dt[NN + r0], d0); }
                if (r0 + 8 < NN) { atomicAdd(&g_dt[r0 + 8], s1); atomicAdd(&g_dt[NN + r0 + 8], d1); }
            }
        }
    }
}

// ---------------- fused GAT aggregate (fp16 gather: one uint4 per lane per edge) ----------------
#define MAXE 64
__device__ __forceinline__ void acc_row(float* acc, float ee, uint4 hv) {
    const __half2* hp2 = (const __half2*)&hv;
    #pragma unroll
    for (int q = 0; q < 4; q++) {
        float2 f = __half22float2(hp2[q]);
        acc[2 * q]     = fmaf(ee, f.x, acc[2 * q]);
        acc[2 * q + 1] = fmaf(ee, f.y, acc[2 * q + 1]);
    }
}

__global__ void __launch_bounds__(256)
k_gat(const float* __restrict__ bias, int dorelu) {
    __shared__ float sv[8][MAXE];
    __shared__ int   ss[8][MAXE];
    int wid = threadIdx.x >> 5, lane = threadIdx.x & 31;
    int n = blockIdx.x * 8 + wid;
    if (n >= NN) return;
    int start = g_rowptr[n], end = g_rowptr[n + 1];
    int deg = end - start;
    float ed = g_dt[NN + n];

    float acc[8] = {};
    float acc2[8] = {};
    float sum = 0.f;
    float m = -3.4e38f;

    if (deg <= MAXE) {
        for (int j0 = 0; j0 < deg; j0 += 32) {
            int j = j0 + lane;
            float v = -3.4e38f;
            if (j < deg) {
                int s = g_csrc[start + j];
                v = g_dt[s] + ed;
                v = v > 0.f ? v : 0.2f * v;
                sv[wid][j] = v;
                ss[wid][j] = s;
            }
            m = fmaxf(m, v);
        }
        #pragma unroll
        for (int o = 16; o > 0; o >>= 1) m = fmaxf(m, __shfl_xor_sync(0xFFFFFFFFu, m, o));
        __syncwarp();
        int j = 0;
        for (; j + 1 < deg; j += 2) {
            float ee0 = __expf(sv[wid][j] - m);
            float ee1 = __expf(sv[wid][j + 1] - m);
            sum += ee0 + ee1;
            uint4 h0 = ((const uint4*)(g_hwh + (size_t)ss[wid][j] * DD))[lane];
            uint4 h1 = ((const uint4*)(g_hwh + (size_t)ss[wid][j + 1] * DD))[lane];
            acc_row(acc, ee0, h0);
            acc_row(acc2, ee1, h1);
        }
        if (j < deg) {
            float ee = __expf(sv[wid][j] - m);
            sum += ee;
            uint4 h0 = ((const uint4*)(g_hwh + (size_t)ss[wid][j] * DD))[lane];
            acc_row(acc, ee, h0);
        }
        #pragma unroll
        for (int q = 0; q < 8; q++) acc[q] += acc2[q];
    } else {
        for (int j = start + lane; j < end; j += 32) {
            float v = g_dt[g_csrc[j]] + ed;
            v = v > 0.f ? v : 0.2f * v;
            m = fmaxf(m, v);
        }
        #pragma unroll
        for (int o = 16; o > 0; o >>= 1) m = fmaxf(m, __shfl_xor_sync(0xFFFFFFFFu, m, o));
        for (int j = start; j < end; j++) {
            int s = g_csrc[j];
            float v = g_dt[s] + ed;
            v = v > 0.f ? v : 0.2f * v;
            float ee = __expf(v - m);
            sum += ee;
            uint4 h0 = ((const uint4*)(g_hwh + (size_t)s * DD))[lane];
            acc_row(acc, ee, h0);
        }
    }
    float inv = (deg > 0) ? 1.0f / sum : 0.f;

    // this lane owns cols 8*lane .. 8*lane+7
    float4 b0 = ((const float4*)bias)[2 * lane];
    float4 b1 = ((const float4*)bias)[2 * lane + 1];
    float o[8] = {acc[0] * inv + b0.x, acc[1] * inv + b0.y,
                  acc[2] * inv + b0.z, acc[3] * inv + b0.w,
                  acc[4] * inv + b1.x, acc[5] * inv + b1.y,
                  acc[6] * inv + b1.z, acc[7] * inv + b1.w};
    if (dorelu) {
        #pragma unroll
        for (int j = 0; j < 8; j++) o[j] = fmaxf(o[j], 0.f);
    }
    __nv_bfloat162 hp[4], lp[4];
    #pragma unroll
    for (int j = 0; j < 4; j++) {
        __nv_bfloat16 h0 = __float2bfloat16(o[2 * j]);
        __nv_bfloat16 h1 = __float2bfloat16(o[2 * j + 1]);
        hp[j] = __halves2bfloat162(h0, h1);
        lp[j] = __halves2bfloat162(__float2bfloat16(o[2 * j] - __bfloat162float(h0)),
                                   __float2bfloat16(o[2 * j + 1] - __bfloat162float(h1)));
    }
    *(uint4*)(g_ahi + (size_t)n * DD + 8 * lane) = *(uint4*)hp;
    *(uint4*)(g_alo + (size_t)n * DD + 8 * lane) = *(uint4*)lp;
}

// ---------------- launch ----------------
extern "C" void kernel_launch(void* const* d_in, const int* in_sizes, int n_in,
                              void* d_out, int out_size) {
    const float* x     = (const float*)d_in[0];
    const void*  ei    = d_in[1];
    const float* W1    = (const float*)d_in[2];
    const float* W2    = (const float*)d_in[3];
    const float* Ws    = (const float*)d_in[4];
    const float* a_src = (const float*)d_in[5];
    const float* a_dst = (const float*)d_in[6];
    const float* bias  = (const float*)d_in[7];
    const float* W3    = (const float*)d_in[8];
    float* out = (float*)d_out;

    float* p_dt;
    __half* p_hwh;
    int* p_deg;
    __nv_bfloat16 *p_ahi, *p_alo, *p_a2hi, *p_a2lo, *p_bhi, *p_blo;
    cudaGetSymbolAddress((void**)&p_hwh,  g_hwh);
    cudaGetSymbolAddress((void**)&p_dt,   g_dt);
    cudaGetSymbolAddress((void**)&p_deg,  g_deg);
    cudaGetSymbolAddress((void**)&p_ahi,  g_ahi);
    cudaGetSymbolAddress((void**)&p_alo,  g_alo);
    cudaGetSymbolAddress((void**)&p_a2hi, g_a2hi);
    cudaGetSymbolAddress((void**)&p_a2lo, g_a2lo);
    cudaGetSymbolAddress((void**)&p_bhi,  g_bhi);
    cudaGetSymbolAddress((void**)&p_blo,  g_blo);

    cudaFuncSetAttribute(k_gemm_mma<0>, cudaFuncAttributeMaxDynamicSharedMemorySize, SMEM_BYTES);
    cudaFuncSetAttribute(k_gemm_mma<1>, cudaFuncAttributeMaxDynamicSharedMemorySize, SMEM_BYTES);
    cudaFuncSetAttribute(k_gemm_mma<2>, cudaFuncAttributeMaxDynamicSharedMemorySize, SMEM_BYTES);

    // one-time: indices, CSR, x split, W12 product, weight splits
    k_detect<<<1, 128>>>((const int*)ei);
    cudaMemsetAsync(p_deg, 0, NN * sizeof(int));
    k_convert<<<(EE + 255) / 256, 256>>>(ei);
    k_scan<<<1, 1024>>>();
    k_fill<<<(EE + 255) / 256, 256>>>();
    k_convA<<<(NN * DD / 8 + 255) / 256, 256>>>(x);
    k_w12<<<dim3(16, 16), dim3(16, 16)>>>(W1, W2);
    k_prepAllB<<<(7 * DD * DD + 255) / 256, 256>>>(Ws, W3);

    dim3 gg(2, (NN + MTILE - 1) / MTILE);   // (2, 313)
    const int BW = DD * DD;

    // h = x @ (W1*W2): split-only emit into S0
    k_gemm_mma<0><<<gg, GT, SMEM_BYTES>>>(nullptr, nullptr, p_a2hi, p_a2lo, p_bhi, p_blo,
                                          p_ahi, p_alo, nullptr, nullptr);

    for (int l = 0; l < 6; l++) {
        cudaMemsetAsync(p_dt, 0, 2 * NN * sizeof(float));
        k_gemm_mma<1><<<gg, GT, SMEM_BYTES>>>(nullptr, p_hwh, p_ahi, p_alo,
                                              p_bhi + (size_t)(2 + l) * BW, p_blo + (size_t)(2 + l) * BW,
                                              nullptr, nullptr, a_src + l * DD, a_dst + l * DD);
        k_gat<<<(NN + 7) / 8, 256>>>(bias + l * DD, l == 5 ? 1 : 0);
    }

    // out = relu(h) @ (W3_top + W3_bot)   (relu folded into last k_gat's split)
    k_gemm_mma<2><<<gg, GT, SMEM_BYTES>>>(out, nullptr, p_ahi, p_alo, p_bhi + 8 * BW, p_blo + 8 * BW,
                                          nullptr, nullptr, nullptr, nullptr);
}